// round 14
// baseline (speedup 1.0000x reference)
#include <cuda_runtime.h>
#include <cstdint>

#define MM 2048
#define NODE 64
#define TT 256
#define RB 16
#define NTHREADS 256
#define NBUF 8                 // W ring: 8 x 16KB = 128KB dynamic smem
#define WBUF_FLOATS 4096
#define XROW 68                // xs row stride (272B): bank shift 4/row

// Scratch (no cudaMalloc allowed): transposed weights (k-major) + softplus table
__device__ __align__(16) float WT_g[TT * NODE * NODE];   // 4 MB
__device__ __align__(16) float st_g[TT * NODE];          // st_g[0][:]=1.0 (IN_SCALE)

// ---------------- phase 0a: W[t][j][k] -> WT[t][k][j] ----------------
__global__ void k_transpose_W(const float* __restrict__ W) {
    __shared__ float tile[64][65];
    int t = blockIdx.x;
    const float* Wt = W + (size_t)t * 4096;
    for (int idx = threadIdx.x; idx < 4096; idx += blockDim.x)
        tile[idx >> 6][idx & 63] = Wt[idx];
    __syncthreads();
    float* O = WT_g + (size_t)t * 4096;
    for (int idx = threadIdx.x; idx < 4096; idx += blockDim.x)
        O[idx] = tile[idx & 63][idx >> 6];   // stride-65 rows -> conflict-free
}

// ---------------- phase 0b: softplus table ----------------
__global__ void k_softplus(const float* __restrict__ ne) {
    int idx = blockIdx.x * blockDim.x + threadIdx.x;
    if (idx >= TT * NODE) return;
    int t = idx >> 6, j = idx & 63;
    float v;
    if (t == 0) v = 1.0f;                       // IN_SCALE at t=0
    else {
        float x = ne[j * TT + t];               // noise_embedding (1, NODE, T)
        v = fmaxf(x, 0.0f) + log1pf(expf(-fabsf(x)));
    }
    st_g[idx] = v;
}

__device__ __forceinline__ void cp_async16(uint32_t dst, const void* src) {
    asm volatile("cp.async.cg.shared.global [%0], [%1], 16;\n" :: "r"(dst), "l"(src));
}

// ---------------- main: two independent 128-thread halves ----------------
// R11 warp shape (8 rows x 4 col-groups; 1-wavefront W and x LDS). Even warps
// own rows 0-7, odd warps rows 8-15 — the halves share ONLY the W ring. Per-
// step sync is a named bar.sync over each half's 128 threads; __syncthreads
// only at 4-step phase boundaries to recycle W ring slots (cp.async refill of
// 4 tiles at once — no cp.async in the per-step path).
__global__ void __launch_bounds__(NTHREADS, 1)
k_chain(const float* __restrict__ b,
        const float* __restrict__ eps0,
        const float* __restrict__ eps,
        float* __restrict__ out)
{
    extern __shared__ float ws[];                  // NBUF * WBUF_FLOATS (W ring)
    __shared__ float xs[2][2][8 * XROW];           // [buf][half][row-local]

    const int tid  = threadIdx.x;
    const int w    = tid >> 5;            // 0..7
    const int ln   = tid & 31;
    const int rl   = ln >> 2;             // 0..7 : row within half
    const int gl   = ln & 3;              // 0..3 : col-group within warp
    const int half = w & 1;               // independent half
    const int r    = half * 8 + rl;       // 0..15 : row within CTA tile
    const int cg   = (w >> 1) * 4 + gl;   // 0..15 : col group (4 cols)
    const int j0   = cg << 2;
    const int m    = blockIdx.x * RB + r;
    const int barid = half + 1;           // named barrier 1 or 2 (0 = syncthreads)

    float* __restrict__ outx = out;
    float* __restrict__ outm = out + (size_t)MM * NODE * TT;
    float* __restrict__ outs = out + 2 * (size_t)MM * NODE * TT;

    const uint32_t ws_base = (uint32_t)__cvta_generic_to_shared(ws);

    // Issue W[tp..tp+3] into ring slots (tq & 7); one commit per call.
    auto prefetch4 = [&](int tp) {
        #pragma unroll
        for (int q = 0; q < 4; ++q) {
            int tq = tp + q;
            if (tq <= 255) {
                const float* src = WT_g + (size_t)tq * WBUF_FLOATS;
                uint32_t dstb = ws_base + (uint32_t)(tq & (NBUF - 1)) * (WBUF_FLOATS * 4);
                #pragma unroll
                for (int i = 0; i < 4; ++i) {
                    int f = tid + i * NTHREADS;            // 1024 x 16B chunks
                    cp_async16(dstb + (uint32_t)f * 16u, src + f * 4);
                }
            }
        }
        asm volatile("cp.async.commit_group;\n");
    };

    prefetch4(1);   // W[1..4] -> slots 1..4

    float xreg[4][4], mreg[4][4], sreg[4][4];   // 4-step staging

    // ---- t = 0: x0 = eps0, m0 = 0, s0 = 1 ----
    {
        float4 e0 = *(const float4*)(eps0 + (size_t)m * NODE + j0);
        xreg[0][0] = e0.x; xreg[0][1] = e0.y; xreg[0][2] = e0.z; xreg[0][3] = e0.w;
        mreg[0][0] = 0.f;  mreg[0][1] = 0.f;  mreg[0][2] = 0.f;  mreg[0][3] = 0.f;
        sreg[0][0] = 1.f;  sreg[0][1] = 1.f;  sreg[0][2] = 1.f;  sreg[0][3] = 1.f;
        *(float4*)&xs[0][half][rl * XROW + j0] = e0;
    }

    // per-step vectors for t=1
    float4 bv = *(const float4*)(b + 64 + j0);
    float4 sv = *(const float4*)(st_g + 64 + j0);
    float4 ev = __ldcs((const float4*)(eps + (size_t)m * NODE + j0));

    int t = 1;
    while (t < TT) {
        // ---- phase boundary (every 4 steps): recycle W ring slots ----
        __syncthreads();                          // slots (t+4..t+7)&7 retired by all
        prefetch4(t + 4);                         // refill with W[t+4..t+7]
        asm volatile("cp.async.wait_group 1;\n"); // W[t..t+3] landed
        __syncthreads();                          // publish to all threads

        #pragma unroll
        for (int q = 0; q < 4; ++q, ++t) {
            if (t >= TT) break;
            const int cur = (t - 1) & 1;
            const int nxt = t & 1;

            // half-private step barrier: x_{t-1} writes visible within half;
            // no thread may proceed to overwrite xs[nxt] while a half-peer
            // still reads it at step t-1.
            asm volatile("bar.sync %0, 128;" :: "r"(barid) : "memory");

            // prefetch per-step vectors for t+1 (hidden under FFMA block)
            const int tp = (t + 1 < TT) ? (t + 1) : t;
            float4 bn = *(const float4*)(b + tp * 64 + j0);
            float4 sn = *(const float4*)(st_g + tp * 64 + j0);
            float4 en = __ldcs((const float4*)(eps + ((size_t)(tp - 1) * MM + m) * NODE + j0));

            float a0 = bv.x, a1 = bv.y, a2 = bv.z, a3 = bv.w;

            const float* xrow = &xs[cur][half][rl * XROW];          // 8 rows, 1 wf
            const float* wt   = ws + (t & (NBUF - 1)) * WBUF_FLOATS;
            const float* wc   = wt + j0;                            // 4 distinct, 1 wf

            #pragma unroll
            for (int kc = 0; kc < 16; ++kc) {
                float4 xv = *(const float4*)(xrow + kc * 4);
                float4 w0 = *(const float4*)(wc + (4 * kc + 0) * 64);
                float4 w1 = *(const float4*)(wc + (4 * kc + 1) * 64);
                float4 w2 = *(const float4*)(wc + (4 * kc + 2) * 64);
                float4 w3 = *(const float4*)(wc + (4 * kc + 3) * 64);
                a0 += xv.x * w0.x; a1 += xv.x * w0.y; a2 += xv.x * w0.z; a3 += xv.x * w0.w;
                a0 += xv.y * w1.x; a1 += xv.y * w1.y; a2 += xv.y * w1.z; a3 += xv.y * w1.w;
                a0 += xv.z * w2.x; a1 += xv.z * w2.y; a2 += xv.z * w2.z; a3 += xv.z * w2.w;
                a0 += xv.w * w3.x; a1 += xv.w * w3.y; a2 += xv.w * w3.z; a3 += xv.w * w3.w;
            }

            float x0 = a0 + sv.x * ev.x;
            float x1 = a1 + sv.y * ev.y;
            float x2 = a2 + sv.z * ev.z;
            float x3 = a3 + sv.w * ev.w;

            const int tl = t & 3;
            mreg[tl][0] = a0;   mreg[tl][1] = a1;   mreg[tl][2] = a2;   mreg[tl][3] = a3;
            xreg[tl][0] = x0;   xreg[tl][1] = x1;   xreg[tl][2] = x2;   xreg[tl][3] = x3;
            sreg[tl][0] = sv.x; sreg[tl][1] = sv.y; sreg[tl][2] = sv.z; sreg[tl][3] = sv.w;

            *(float4*)&xs[nxt][half][rl * XROW + j0] = make_float4(x0, x1, x2, x3);

            bv = bn; sv = sn; ev = en;

            // ---- flush every 4 steps: reversed, 16B-aligned float4 ----
            if (tl == 3) {
                const int ch    = t >> 2;          // chunk 0..63 covers t=4ch..4ch+3
                const int obase = 252 - 4 * ch;    // out offset of t=4ch+3
                #pragma unroll
                for (int i = 0; i < 4; ++i) {
                    size_t base = ((size_t)m * NODE + j0 + i) * TT + obase;
                    __stcs((float4*)(outx + base), make_float4(xreg[3][i], xreg[2][i], xreg[1][i], xreg[0][i]));
                    __stcs((float4*)(outm + base), make_float4(mreg[3][i], mreg[2][i], mreg[1][i], mreg[0][i]));
                    __stcs((float4*)(outs + base), make_float4(sreg[3][i], sreg[2][i], sreg[1][i], sreg[0][i]));
                }
            }
        }
    }
}

extern "C" void kernel_launch(void* const* d_in, const int* in_sizes, int n_in,
                              void* d_out, int out_size) {
    const float* W    = (const float*)d_in[0];   // (T, NODE, NODE)
    const float* b    = (const float*)d_in[1];   // (T, NODE)
    const float* ne   = (const float*)d_in[2];   // (1, NODE, T)
    const float* eps0 = (const float*)d_in[3];   // (M, NODE)
    const float* eps  = (const float*)d_in[4];   // (T-1, M, NODE)
    float* out = (float*)d_out;                  // [x | m | s], each (M, NODE, T)

    // Idempotent attribute set (not a stream op; capture-safe)
    cudaFuncSetAttribute(k_chain, cudaFuncAttributeMaxDynamicSharedMemorySize,
                         NBUF * WBUF_FLOATS * 4);

    k_transpose_W<<<TT, 256>>>(W);
    k_softplus<<<(TT * NODE + 255) / 256, 256>>>(ne);
    k_chain<<<MM / RB, NTHREADS, NBUF * WBUF_FLOATS * 4>>>(b, eps0, eps, out);
}

// round 15
// speedup vs baseline: 1.1844x; 1.1844x over previous
#include <cuda_runtime.h>
#include <cstdint>

#define MM 2048
#define NODE 64
#define TT 256
#define RB 8                   // rows per CTA
#define NTHREADS 128
#define XROW 68                // xs row stride (272B): bank shift 4/row

// Scratch (no cudaMalloc allowed): transposed weights (k-major) + softplus table
__device__ __align__(16) float WT_g[TT * NODE * NODE];   // 4 MB
__device__ __align__(16) float st_g[TT * NODE];          // st_g[0][:]=1.0 (IN_SCALE)

// ---------------- phase 0a: W[t][j][k] -> WT[t][k][j] ----------------
__global__ void k_transpose_W(const float* __restrict__ W) {
    __shared__ float tile[64][65];
    int t = blockIdx.x;
    const float* Wt = W + (size_t)t * 4096;
    for (int idx = threadIdx.x; idx < 4096; idx += blockDim.x)
        tile[idx >> 6][idx & 63] = Wt[idx];
    __syncthreads();
    float* O = WT_g + (size_t)t * 4096;
    for (int idx = threadIdx.x; idx < 4096; idx += blockDim.x)
        O[idx] = tile[idx & 63][idx >> 6];   // stride-65 rows -> conflict-free
}

// ---------------- phase 0b: softplus table ----------------
__global__ void k_softplus(const float* __restrict__ ne) {
    int idx = blockIdx.x * blockDim.x + threadIdx.x;
    if (idx >= TT * NODE) return;
    int t = idx >> 6, j = idx & 63;
    float v;
    if (t == 0) v = 1.0f;                       // IN_SCALE at t=0
    else {
        float x = ne[j * TT + t];               // noise_embedding (1, NODE, T)
        v = fmaxf(x, 0.0f) + log1pf(expf(-fabsf(x)));
    }
    st_g[idx] = v;
}

__device__ __forceinline__ void cp_async16(uint32_t dst, const void* src) {
    asm volatile("cp.async.cg.shared.global [%0], [%1], 16;\n" :: "r"(dst), "l"(src));
}

// ---------------- main: R11 pipeline, 2 independent CTAs per SM ----------------
// 128 threads, RB=8 rows, grid 256, 2 CTAs co-resident per SM (independent
// barriers + cp.async streams -> HW interleaving covers each other's stalls).
// Warp = 8 rows x 4 col-groups: W LDS = 4 distinct 16B (1 wavefront, 8x bcast),
// x LDS = 8 distinct 16B (1 wavefront, 4x bcast). Scalar FFMA core. Per-step
// W double-buffer via cp.async (16KB/step, smooth). x-row preloaded into
// registers right after the barrier.
__global__ void __launch_bounds__(NTHREADS, 2)
k_chain(const float* __restrict__ b,
        const float* __restrict__ eps0,
        const float* __restrict__ eps,
        float* __restrict__ out)
{
    // W double buffer: Wsh[buf][k][j-group] — 32 KB
    __shared__ float4 Wsh[2][NODE][NODE / 4];
    // x double buffer, rows padded to 272B
    __shared__ float xs[2][RB * XROW];

    const int tid = threadIdx.x;
    const int w   = tid >> 5;             // 0..3
    const int ln  = tid & 31;
    const int rl  = ln >> 2;              // 0..7 : row within CTA
    const int gl  = ln & 3;               // 0..3 : col-group within warp
    const int r   = rl;                   // 0..7
    const int cg  = w * 4 + gl;           // 0..15 : col group (4 cols)
    const int j0  = cg << 2;
    const int m   = blockIdx.x * RB + r;

    float* __restrict__ outx = out;
    float* __restrict__ outm = out + (size_t)MM * NODE * TT;
    float* __restrict__ outs = out + 2 * (size_t)MM * NODE * TT;

    const uint32_t wsh_base = (uint32_t)__cvta_generic_to_shared(&Wsh[0][0][0]);

    // Prefetch W[1] into buffer 1 (buffer parity == t&1); linear 16KB copy.
    {
        const float* src = WT_g + 4096;
        #pragma unroll
        for (int i = 0; i < 8; i++) {
            int f = tid + i * NTHREADS;
            cp_async16(wsh_base + 16384u + (uint32_t)f * 16u, src + f * 4);
        }
        asm volatile("cp.async.commit_group;\n");
    }

    float xreg[4][4], mreg[4][4], sreg[4][4];   // 4-step output staging

    // ---- t = 0: x0 = eps0, m0 = 0, s0 = 1 ----
    {
        float4 e0 = *(const float4*)(eps0 + (size_t)m * NODE + j0);
        xreg[0][0] = e0.x; xreg[0][1] = e0.y; xreg[0][2] = e0.z; xreg[0][3] = e0.w;
        mreg[0][0] = 0.f;  mreg[0][1] = 0.f;  mreg[0][2] = 0.f;  mreg[0][3] = 0.f;
        sreg[0][0] = 1.f;  sreg[0][1] = 1.f;  sreg[0][2] = 1.f;  sreg[0][3] = 1.f;
        *(float4*)&xs[0][r * XROW + j0] = e0;
    }

    // Prefetch per-step vectors for t=1 (registers)
    float4 bv = *(const float4*)(b + 64 + j0);
    float4 sv = *(const float4*)(st_g + 64 + j0);
    float4 ev = __ldcs((const float4*)(eps + (size_t)m * NODE + j0));

    #pragma unroll 1
    for (int t = 1; t < TT; ++t) {
        const int cur = (t - 1) & 1;
        const int nxt = t & 1;

        // 1) W[t] landed. 2) Barrier: retired buffer free, xs[cur] visible.
        asm volatile("cp.async.wait_group 0;\n");
        __syncthreads();

        // Preload the full x row into registers (16 independent LDS.128,
        // issued before anything else post-barrier).
        const float* xrow = &xs[cur][r * XROW];
        float4 xv16[16];
        #pragma unroll
        for (int kc = 0; kc < 16; ++kc)
            xv16[kc] = *(const float4*)(xrow + kc * 4);

        // 3) Prefetch W[t+1] into retired buffer (overlaps FFMA block).
        if (t + 1 < TT) {
            const float* src = WT_g + (size_t)(t + 1) * 4096;
            uint32_t dstb = wsh_base + (uint32_t)((t + 1) & 1) * 16384u;
            #pragma unroll
            for (int i = 0; i < 8; i++) {
                int f = tid + i * NTHREADS;
                cp_async16(dstb + (uint32_t)f * 16u, src + f * 4);
            }
            asm volatile("cp.async.commit_group;\n");
        }

        // Prefetch per-step vectors for t+1 (hidden under FFMA block)
        const int tp = (t + 1 < TT) ? (t + 1) : t;
        float4 bn = *(const float4*)(b + tp * 64 + j0);
        float4 sn = *(const float4*)(st_g + tp * 64 + j0);
        float4 en = __ldcs((const float4*)(eps + ((size_t)(tp - 1) * MM + m) * NODE + j0));

        float a0 = bv.x, a1 = bv.y, a2 = bv.z, a3 = bv.w;

        const float4* wcol = &Wsh[nxt][0][cg];   // lane gl -> 4 distinct 16B, 8x bcast

        #pragma unroll
        for (int kc = 0; kc < 16; ++kc) {
            float4 xv = xv16[kc];
            float4 w0 = wcol[(4 * kc + 0) * 16];
            float4 w1 = wcol[(4 * kc + 1) * 16];
            float4 w2 = wcol[(4 * kc + 2) * 16];
            float4 w3 = wcol[(4 * kc + 3) * 16];
            a0 += xv.x * w0.x; a1 += xv.x * w0.y; a2 += xv.x * w0.z; a3 += xv.x * w0.w;
            a0 += xv.y * w1.x; a1 += xv.y * w1.y; a2 += xv.y * w1.z; a3 += xv.y * w1.w;
            a0 += xv.z * w2.x; a1 += xv.z * w2.y; a2 += xv.z * w2.z; a3 += xv.z * w2.w;
            a0 += xv.w * w3.x; a1 += xv.w * w3.y; a2 += xv.w * w3.z; a3 += xv.w * w3.w;
        }

        float x0 = a0 + sv.x * ev.x;
        float x1 = a1 + sv.y * ev.y;
        float x2 = a2 + sv.z * ev.z;
        float x3 = a3 + sv.w * ev.w;

        const int tl = t & 3;
        mreg[tl][0] = a0;   mreg[tl][1] = a1;   mreg[tl][2] = a2;   mreg[tl][3] = a3;
        xreg[tl][0] = x0;   xreg[tl][1] = x1;   xreg[tl][2] = x2;   xreg[tl][3] = x3;
        sreg[tl][0] = sv.x; sreg[tl][1] = sv.y; sreg[tl][2] = sv.z; sreg[tl][3] = sv.w;

        *(float4*)&xs[nxt][r * XROW + j0] = make_float4(x0, x1, x2, x3);

        bv = bn; sv = sn; ev = en;

        // ---- flush every 4 steps: reversed, 16B-aligned float4 ----
        if (tl == 3) {
            const int ch    = t >> 2;          // chunk 0..63 covers t=4ch..4ch+3
            const int obase = 252 - 4 * ch;    // out offset of t=4ch+3
            #pragma unroll
            for (int i = 0; i < 4; ++i) {
                size_t base = ((size_t)m * NODE + j0 + i) * TT + obase;
                __stcs((float4*)(outx + base), make_float4(xreg[3][i], xreg[2][i], xreg[1][i], xreg[0][i]));
                __stcs((float4*)(outm + base), make_float4(mreg[3][i], mreg[2][i], mreg[1][i], mreg[0][i]));
                __stcs((float4*)(outs + base), make_float4(sreg[3][i], sreg[2][i], sreg[1][i], sreg[0][i]));
            }
        }
    }
}

extern "C" void kernel_launch(void* const* d_in, const int* in_sizes, int n_in,
                              void* d_out, int out_size) {
    const float* W    = (const float*)d_in[0];   // (T, NODE, NODE)
    const float* b    = (const float*)d_in[1];   // (T, NODE)
    const float* ne   = (const float*)d_in[2];   // (1, NODE, T)
    const float* eps0 = (const float*)d_in[3];   // (M, NODE)
    const float* eps  = (const float*)d_in[4];   // (T-1, M, NODE)
    float* out = (float*)d_out;                  // [x | m | s], each (M, NODE, T)

    k_transpose_W<<<TT, 256>>>(W);
    k_softplus<<<(TT * NODE + 255) / 256, 256>>>(ne);
    k_chain<<<MM / RB, NTHREADS>>>(b, eps0, eps, out);
}

// round 16
// speedup vs baseline: 1.3027x; 1.0999x over previous
#include <cuda_runtime.h>
#include <cstdint>

#define MM 2048
#define NODE 64
#define TT 256
#define RB 16
#define NTHREADS 256
#define XROW 68            // xs row stride in floats (272B): conflict-free x loads

// Scratch (no cudaMalloc allowed): transposed weights (k-major) + softplus table
__device__ __align__(16) float WT_g[TT * NODE * NODE];   // 4 MB
__device__ __align__(16) float st_g[TT * NODE];          // 64 KB, st_g[0][:]=1.0

// ---------------- phase 0 (merged): transpose W + softplus table ----------------
// Blocks 0..TT-1: W[t][j][k] -> WT[t][k][j].  Block TT: softplus table.
// Merged so the launch stream is P,C,P,C,... and ncu (-s 5 -c 1) captures k_chain.
__global__ void k_prep(const float* __restrict__ W, const float* __restrict__ ne) {
    int t = blockIdx.x;
    if (t < TT) {
        __shared__ float tile[64][65];
        const float* Wt = W + (size_t)t * 4096;
        for (int idx = threadIdx.x; idx < 4096; idx += blockDim.x)
            tile[idx >> 6][idx & 63] = Wt[idx];
        __syncthreads();
        float* O = WT_g + (size_t)t * 4096;
        for (int idx = threadIdx.x; idx < 4096; idx += blockDim.x)
            O[idx] = tile[idx & 63][idx >> 6];   // stride-65 rows -> conflict-free
    } else {
        for (int idx = threadIdx.x; idx < TT * NODE; idx += blockDim.x) {
            int tt = idx >> 6, j = idx & 63;
            float v;
            if (tt == 0) v = 1.0f;                  // IN_SCALE at t=0
            else {
                float x = ne[j * TT + tt];          // noise_embedding (1, NODE, T)
                v = fmaxf(x, 0.0f) + log1pf(expf(-fabsf(x)));
            }
            st_g[idx] = v;
        }
    }
}

__device__ __forceinline__ void cp_async16(uint32_t dst, const void* src) {
    asm volatile("cp.async.cg.shared.global [%0], [%1], 16;\n" :: "r"(dst), "l"(src));
}

// ---------------- main: fused 255-step recurrence (R11 shape) ----------------
// Warp = 8 rows x 4 col-groups: W LDS = 4 distinct 16B (1 wavefront, 8x bcast),
// x LDS = 8 distinct 16B (1 wavefront, 4x bcast). Scalar FFMA, 8 accumulators
// (even/odd kc) to halve the serial-dependency chain. x row preloaded into
// registers post-barrier. Per-step 16KB W double-buffer via cp.async.
__global__ void __launch_bounds__(NTHREADS, 1)
k_chain(const float* __restrict__ b,
        const float* __restrict__ eps0,
        const float* __restrict__ eps,
        float* __restrict__ out)
{
    // W double buffer: Wsh[buf][k][j-group] — 32 KB
    __shared__ float4 Wsh[2][NODE][NODE / 4];
    // x double buffer, rows padded to 272B
    __shared__ float xs[2][RB * XROW];

    const int tid = threadIdx.x;
    const int w   = tid >> 5;             // 0..7
    const int ln  = tid & 31;
    const int rl  = ln >> 2;              // 0..7 : row within warp
    const int gl  = ln & 3;               // 0..3 : col-group within warp
    const int r   = (w & 1) * 8 + rl;     // 0..15 : row within CTA tile
    const int cg  = (w >> 1) * 4 + gl;    // 0..15 : col group (4 cols)
    const int j0  = cg << 2;
    const int m   = blockIdx.x * RB + r;

    float* __restrict__ outx = out;
    float* __restrict__ outm = out + (size_t)MM * NODE * TT;
    float* __restrict__ outs = out + 2 * (size_t)MM * NODE * TT;

    const uint32_t wsh_base = (uint32_t)__cvta_generic_to_shared(&Wsh[0][0][0]);

    // Prefetch W[1] into buffer 1 (buffer parity == t&1); linear 16KB copy.
    {
        const float* src = WT_g + 4096;
        #pragma unroll
        for (int i = 0; i < 4; i++) {
            int f = tid + i * 256;
            cp_async16(wsh_base + 16384u + (uint32_t)f * 16u, src + f * 4);
        }
        asm volatile("cp.async.commit_group;\n");
    }

    float xreg[8][4], mreg[8][4];   // 8-step output staging (32B-aligned stores)

    // ---- t = 0: x0 = eps0, m0 = 0 ----
    {
        float4 e0 = *(const float4*)(eps0 + (size_t)m * NODE + j0);
        xreg[0][0] = e0.x; xreg[0][1] = e0.y; xreg[0][2] = e0.z; xreg[0][3] = e0.w;
        mreg[0][0] = 0.f;  mreg[0][1] = 0.f;  mreg[0][2] = 0.f;  mreg[0][3] = 0.f;
        *(float4*)&xs[0][r * XROW + j0] = e0;
    }

    // Prefetch per-step vectors for t=1 (registers)
    float4 bv = *(const float4*)(b + 64 + j0);
    float4 sv = *(const float4*)(st_g + 64 + j0);
    float4 ev = __ldcs((const float4*)(eps + (size_t)m * NODE + j0));

    #pragma unroll 1
    for (int t = 1; t < TT; ++t) {
        const int cur = (t - 1) & 1;
        const int nxt = t & 1;

        // 1) W[t] landed. 2) Barrier: retired buffer free, xs[cur] visible.
        asm volatile("cp.async.wait_group 0;\n");
        __syncthreads();

        // Preload full x row into registers: 16 independent LDS.128, MLP=16.
        const float* xrow = &xs[cur][r * XROW];
        float4 xv16[16];
        #pragma unroll
        for (int kc = 0; kc < 16; ++kc)
            xv16[kc] = *(const float4*)(xrow + kc * 4);

        // 3) Prefetch W[t+1] into retired buffer (overlaps FFMA block).
        if (t + 1 < TT) {
            const float* src = WT_g + (size_t)(t + 1) * 4096;
            uint32_t dstb = wsh_base + (uint32_t)((t + 1) & 1) * 16384u;
            #pragma unroll
            for (int i = 0; i < 4; i++) {
                int f = tid + i * 256;
                cp_async16(dstb + (uint32_t)f * 16u, src + f * 4);
            }
            asm volatile("cp.async.commit_group;\n");
        }

        // Prefetch per-step vectors for t+1 (hidden under FFMA block)
        const int tp = (t + 1 < TT) ? (t + 1) : t;
        float4 bn = *(const float4*)(b + tp * 64 + j0);
        float4 sn = *(const float4*)(st_g + tp * 64 + j0);
        float4 en = __ldcs((const float4*)(eps + ((size_t)(tp - 1) * MM + m) * NODE + j0));

        // 8 accumulators: even/odd kc chains (serial depth 32 instead of 64)
        float a0 = bv.x, a1 = bv.y, a2 = bv.z, a3 = bv.w;
        float c0 = 0.f,  c1 = 0.f,  c2 = 0.f,  c3 = 0.f;

        const float4* wcol = &Wsh[nxt][0][cg];   // lane gl -> 4 distinct 16B, 8x bcast

        #pragma unroll
        for (int kc = 0; kc < 16; kc += 2) {
            {
                float4 xv = xv16[kc];
                float4 w0 = wcol[(4 * kc + 0) * 16];
                float4 w1 = wcol[(4 * kc + 1) * 16];
                float4 w2 = wcol[(4 * kc + 2) * 16];
                float4 w3 = wcol[(4 * kc + 3) * 16];
                a0 += xv.x * w0.x; a1 += xv.x * w0.y; a2 += xv.x * w0.z; a3 += xv.x * w0.w;
                a0 += xv.y * w1.x; a1 += xv.y * w1.y; a2 += xv.y * w1.z; a3 += xv.y * w1.w;
                a0 += xv.z * w2.x; a1 += xv.z * w2.y; a2 += xv.z * w2.z; a3 += xv.z * w2.w;
                a0 += xv.w * w3.x; a1 += xv.w * w3.y; a2 += xv.w * w3.z; a3 += xv.w * w3.w;
            }
            {
                float4 xv = xv16[kc + 1];
                float4 w0 = wcol[(4 * kc + 4) * 16];
                float4 w1 = wcol[(4 * kc + 5) * 16];
                float4 w2 = wcol[(4 * kc + 6) * 16];
                float4 w3 = wcol[(4 * kc + 7) * 16];
                c0 += xv.x * w0.x; c1 += xv.x * w0.y; c2 += xv.x * w0.z; c3 += xv.x * w0.w;
                c0 += xv.y * w1.x; c1 += xv.y * w1.y; c2 += xv.y * w1.z; c3 += xv.y * w1.w;
                c0 += xv.z * w2.x; c1 += xv.z * w2.y; c2 += xv.z * w2.z; c3 += xv.z * w2.w;
                c0 += xv.w * w3.x; c1 += xv.w * w3.y; c2 += xv.w * w3.z; c3 += xv.w * w3.w;
            }
        }
        a0 += c0; a1 += c1; a2 += c2; a3 += c3;

        float x0 = a0 + sv.x * ev.x;
        float x1 = a1 + sv.y * ev.y;
        float x2 = a2 + sv.z * ev.z;
        float x3 = a3 + sv.w * ev.w;

        const int tl = t & 7;
        mreg[tl][0] = a0; mreg[tl][1] = a1; mreg[tl][2] = a2; mreg[tl][3] = a3;
        xreg[tl][0] = x0; xreg[tl][1] = x1; xreg[tl][2] = x2; xreg[tl][3] = x3;

        *(float4*)&xs[nxt][r * XROW + j0] = make_float4(x0, x1, x2, x3);

        bv = bn; sv = sn; ev = en;

        // ---- flush every 8 steps: reversed, 32B-aligned float4 pairs ----
        if (tl == 7) {
            const int cch   = t >> 3;            // chunk id, 0..31
            const int obase = 248 - 8 * cch;     // out offset of t = 8c+7 .. 8c
            float sreg[8][4];
            #pragma unroll
            for (int u = 0; u < 8; ++u) {
                float4 s4 = *(const float4*)(st_g + (8 * cch + u) * NODE + j0);
                sreg[u][0] = s4.x; sreg[u][1] = s4.y; sreg[u][2] = s4.z; sreg[u][3] = s4.w;
            }
            #pragma unroll
            for (int i = 0; i < 4; ++i) {
                size_t base = ((size_t)m * NODE + j0 + i) * TT + obase;
                __stcs((float4*)(outx + base),     make_float4(xreg[7][i], xreg[6][i], xreg[5][i], xreg[4][i]));
                __stcs((float4*)(outx + base + 4), make_float4(xreg[3][i], xreg[2][i], xreg[1][i], xreg[0][i]));
                __stcs((float4*)(outm + base),     make_float4(mreg[7][i], mreg[6][i], mreg[5][i], mreg[4][i]));
                __stcs((float4*)(outm + base + 4), make_float4(mreg[3][i], mreg[2][i], mreg[1][i], mreg[0][i]));
                __stcs((float4*)(outs + base),     make_float4(sreg[7][i], sreg[6][i], sreg[5][i], sreg[4][i]));
                __stcs((float4*)(outs + base + 4), make_float4(sreg[3][i], sreg[2][i], sreg[1][i], sreg[0][i]));
            }
        }
    }
}

extern "C" void kernel_launch(void* const* d_in, const int* in_sizes, int n_in,
                              void* d_out, int out_size) {
    const float* W    = (const float*)d_in[0];   // (T, NODE, NODE)
    const float* b    = (const float*)d_in[1];   // (T, NODE)
    const float* ne   = (const float*)d_in[2];   // (1, NODE, T)
    const float* eps0 = (const float*)d_in[3];   // (M, NODE)
    const float* eps  = (const float*)d_in[4];   // (T-1, M, NODE)
    float* out = (float*)d_out;                  // [x | m | s], each (M, NODE, T)

    k_prep<<<TT + 1, 256>>>(W, ne);
    k_chain<<<MM / RB, NTHREADS>>>(b, eps0, eps, out);
}

// round 17
// speedup vs baseline: 1.3038x; 1.0008x over previous
#include <cuda_runtime.h>
#include <cstdint>

#define MM 2048
#define NODE 64
#define TT 256
#define RB 16
#define NTHREADS 256
#define XROW 68            // xs row stride in floats (272B): conflict-free x loads
#define WTILE_BYTES 16384

// Scratch (no cudaMalloc allowed): transposed weights (k-major) + softplus table
__device__ __align__(16) float WT_g[TT * NODE * NODE];   // 4 MB
__device__ __align__(16) float st_g[TT * NODE];          // 64 KB, st_g[0][:]=1.0

// ---------------- phase 0 (merged): transpose W + softplus table ----------------
__global__ void k_prep(const float* __restrict__ W, const float* __restrict__ ne) {
    int t = blockIdx.x;
    if (t < TT) {
        __shared__ float tile[64][65];
        const float* Wt = W + (size_t)t * 4096;
        for (int idx = threadIdx.x; idx < 4096; idx += blockDim.x)
            tile[idx >> 6][idx & 63] = Wt[idx];
        __syncthreads();
        float* O = WT_g + (size_t)t * 4096;
        for (int idx = threadIdx.x; idx < 4096; idx += blockDim.x)
            O[idx] = tile[idx & 63][idx >> 6];   // stride-65 rows -> conflict-free
    } else {
        for (int idx = threadIdx.x; idx < TT * NODE; idx += blockDim.x) {
            int tt = idx >> 6, j = idx & 63;
            float v;
            if (tt == 0) v = 1.0f;                  // IN_SCALE at t=0
            else {
                float x = ne[j * TT + tt];          // noise_embedding (1, NODE, T)
                v = fmaxf(x, 0.0f) + log1pf(expf(-fabsf(x)));
            }
            st_g[idx] = v;
        }
    }
}

// ---- mbarrier + bulk-async helpers ----
#define MBAR_INIT(mbar, cnt) \
    asm volatile("mbarrier.init.shared.b64 [%0], %1;" :: "r"(mbar), "r"(cnt) : "memory")
#define MBAR_EXPECT_TX(mbar, bytes) \
    asm volatile("mbarrier.arrive.expect_tx.shared.b64 _, [%0], %1;" :: "r"(mbar), "r"(bytes) : "memory")
#define MBAR_WAIT(mbar, parity) do {                                           \
    asm volatile(                                                              \
        "{\n\t.reg .pred P;\n\t"                                               \
        "WAIT_%=:\n\t"                                                         \
        "mbarrier.try_wait.parity.acquire.cta.shared::cta.b64 P, [%0], %1, 0x989680;\n\t" \
        "@P bra.uni DONE_%=;\n\t"                                              \
        "bra.uni WAIT_%=;\n\t"                                                 \
        "DONE_%=:\n\t}"                                                        \
        :: "r"(mbar), "r"(parity) : "memory");                                 \
} while (0)

__device__ __forceinline__ void bulk_copy_g2s(uint32_t dst_smem, const void* src,
                                              uint32_t bytes, uint32_t mbar) {
    asm volatile(
        "cp.async.bulk.shared::cta.global.mbarrier::complete_tx::bytes [%0], [%1], %2, [%3];"
        :: "r"(dst_smem), "l"(src), "r"(bytes), "r"(mbar) : "memory");
}

// ---------------- main: fused 255-step recurrence ----------------
// R16 core (8 rows x 4 col-groups per warp, 1-wavefront W/x LDS, 8 accumulator
// chains, x-row register preload). W double-buffer now filled by ONE
// cp.async.bulk (TMA) per step instead of 1024 per-thread cp.async ops —
// removes ~2048 cyc/SMSP/step of LDGSTS issue occupancy (rt=8 cyc/op).
__global__ void __launch_bounds__(NTHREADS, 1)
k_chain(const float* __restrict__ b,
        const float* __restrict__ eps0,
        const float* __restrict__ eps,
        float* __restrict__ out)
{
    __shared__ float4 Wsh[2][NODE][NODE / 4];      // 32 KB W double buffer
    __shared__ float xs[2][RB * XROW];             // x double buffer
    __shared__ __align__(8) unsigned long long mbar[2];

    const int tid = threadIdx.x;
    const int w   = tid >> 5;             // 0..7
    const int ln  = tid & 31;
    const int rl  = ln >> 2;              // 0..7 : row within warp
    const int gl  = ln & 3;               // 0..3 : col-group within warp
    const int r   = (w & 1) * 8 + rl;     // 0..15 : row within CTA tile
    const int cg  = (w >> 1) * 4 + gl;    // 0..15 : col group (4 cols)
    const int j0  = cg << 2;
    const int m   = blockIdx.x * RB + r;

    float* __restrict__ outx = out;
    float* __restrict__ outm = out + (size_t)MM * NODE * TT;
    float* __restrict__ outs = out + 2 * (size_t)MM * NODE * TT;

    const uint32_t wsh_base = (uint32_t)__cvta_generic_to_shared(&Wsh[0][0][0]);
    const uint32_t mbar0 = (uint32_t)__cvta_generic_to_shared(&mbar[0]);
    const uint32_t mbar1 = (uint32_t)__cvta_generic_to_shared(&mbar[1]);

    // ---- prologue: init barriers, issue W[1] into buffer 1 ----
    if (tid == 0) {
        MBAR_INIT(mbar0, 1);
        MBAR_INIT(mbar1, 1);
    }
    __syncthreads();
    if (tid == 0) {
        MBAR_EXPECT_TX(mbar1, WTILE_BYTES);
        bulk_copy_g2s(wsh_base + 16384u, WT_g + 4096, WTILE_BYTES, mbar1);
    }
    int ph0 = 0, ph1 = 0;   // per-buffer phase parity

    float xreg[8][4], mreg[8][4];   // 8-step output staging (32B-aligned stores)

    // ---- t = 0: x0 = eps0, m0 = 0 ----
    {
        float4 e0 = *(const float4*)(eps0 + (size_t)m * NODE + j0);
        xreg[0][0] = e0.x; xreg[0][1] = e0.y; xreg[0][2] = e0.z; xreg[0][3] = e0.w;
        mreg[0][0] = 0.f;  mreg[0][1] = 0.f;  mreg[0][2] = 0.f;  mreg[0][3] = 0.f;
        *(float4*)&xs[0][r * XROW + j0] = e0;
    }

    // Prefetch per-step vectors for t=1 (registers)
    float4 bv = *(const float4*)(b + 64 + j0);
    float4 sv = *(const float4*)(st_g + 64 + j0);
    float4 ev = __ldcs((const float4*)(eps + (size_t)m * NODE + j0));

    #pragma unroll 1
    for (int t = 1; t < TT; ++t) {
        const int cur = (t - 1) & 1;
        const int nxt = t & 1;

        // Barrier: xs[cur] writes visible; W buffer (t+1)&1 retired by all
        // readers (they finished step t-1) -> safe to overwrite via TMA.
        __syncthreads();

        // One elected thread issues the 16KB bulk copy for W[t+1].
        if (tid == 0 && t + 1 < TT) {
            const uint32_t pb   = (t + 1) & 1;
            const uint32_t mb   = pb ? mbar1 : mbar0;
            MBAR_EXPECT_TX(mb, WTILE_BYTES);
            bulk_copy_g2s(wsh_base + pb * 16384u,
                          WT_g + (size_t)(t + 1) * 4096, WTILE_BYTES, mb);
        }

        // Wait for W[t] (acquire orders subsequent LDS after TMA data).
        if (nxt) { MBAR_WAIT(mbar1, ph1); ph1 ^= 1; }
        else     { MBAR_WAIT(mbar0, ph0); ph0 ^= 1; }

        // Preload full x row into registers: 16 independent LDS.128, MLP=16.
        const float* xrow = &xs[cur][r * XROW];
        float4 xv16[16];
        #pragma unroll
        for (int kc = 0; kc < 16; ++kc)
            xv16[kc] = *(const float4*)(xrow + kc * 4);

        // Prefetch per-step vectors for t+1 (hidden under FFMA block)
        const int tp = (t + 1 < TT) ? (t + 1) : t;
        float4 bn = *(const float4*)(b + tp * 64 + j0);
        float4 sn = *(const float4*)(st_g + tp * 64 + j0);
        float4 en = __ldcs((const float4*)(eps + ((size_t)(tp - 1) * MM + m) * NODE + j0));

        // 8 accumulators: even/odd kc chains (serial depth 32)
        float a0 = bv.x, a1 = bv.y, a2 = bv.z, a3 = bv.w;
        float c0 = 0.f,  c1 = 0.f,  c2 = 0.f,  c3 = 0.f;

        const float4* wcol = &Wsh[nxt][0][cg];   // lane gl -> 4 distinct 16B, 8x bcast

        #pragma unroll
        for (int kc = 0; kc < 16; kc += 2) {
            {
                float4 xv = xv16[kc];
                float4 w0 = wcol[(4 * kc + 0) * 16];
                float4 w1 = wcol[(4 * kc + 1) * 16];
                float4 w2 = wcol[(4 * kc + 2) * 16];
                float4 w3 = wcol[(4 * kc + 3) * 16];
                a0 += xv.x * w0.x; a1 += xv.x * w0.y; a2 += xv.x * w0.z; a3 += xv.x * w0.w;
                a0 += xv.y * w1.x; a1 += xv.y * w1.y; a2 += xv.y * w1.z; a3 += xv.y * w1.w;
                a0 += xv.z * w2.x; a1 += xv.z * w2.y; a2 += xv.z * w2.z; a3 += xv.z * w2.w;
                a0 += xv.w * w3.x; a1 += xv.w * w3.y; a2 += xv.w * w3.z; a3 += xv.w * w3.w;
            }
            {
                float4 xv = xv16[kc + 1];
                float4 w0 = wcol[(4 * kc + 4) * 16];
                float4 w1 = wcol[(4 * kc + 5) * 16];
                float4 w2 = wcol[(4 * kc + 6) * 16];
                float4 w3 = wcol[(4 * kc + 7) * 16];
                c0 += xv.x * w0.x; c1 += xv.x * w0.y; c2 += xv.x * w0.z; c3 += xv.x * w0.w;
                c0 += xv.y * w1.x; c1 += xv.y * w1.y; c2 += xv.y * w1.z; c3 += xv.y * w1.w;
                c0 += xv.z * w2.x; c1 += xv.z * w2.y; c2 += xv.z * w2.z; c3 += xv.z * w2.w;
                c0 += xv.w * w3.x; c1 += xv.w * w3.y; c2 += xv.w * w3.z; c3 += xv.w * w3.w;
            }
        }
        a0 += c0; a1 += c1; a2 += c2; a3 += c3;

        float x0 = a0 + sv.x * ev.x;
        float x1 = a1 + sv.y * ev.y;
        float x2 = a2 + sv.z * ev.z;
        float x3 = a3 + sv.w * ev.w;

        const int tl = t & 7;
        mreg[tl][0] = a0; mreg[tl][1] = a1; mreg[tl][2] = a2; mreg[tl][3] = a3;
        xreg[tl][0] = x0; xreg[tl][1] = x1; xreg[tl][2] = x2; xreg[tl][3] = x3;

        *(float4*)&xs[nxt][r * XROW + j0] = make_float4(x0, x1, x2, x3);

        bv = bn; sv = sn; ev = en;

        // ---- flush every 8 steps: reversed, 32B-aligned float4 pairs ----
        if (tl == 7) {
            const int cch   = t >> 3;            // chunk id, 0..31
            const int obase = 248 - 8 * cch;     // out offset of t = 8c+7 .. 8c
            float sreg[8][4];
            #pragma unroll
            for (int u = 0; u < 8; ++u) {
                float4 s4 = *(const float4*)(st_g + (8 * cch + u) * NODE + j0);
                sreg[u][0] = s4.x; sreg[u][1] = s4.y; sreg[u][2] = s4.z; sreg[u][3] = s4.w;
            }
            #pragma unroll
            for (int i = 0; i < 4; ++i) {
                size_t base = ((size_t)m * NODE + j0 + i) * TT + obase;
                __stcs((float4*)(outx + base),     make_float4(xreg[7][i], xreg[6][i], xreg[5][i], xreg[4][i]));
                __stcs((float4*)(outx + base + 4), make_float4(xreg[3][i], xreg[2][i], xreg[1][i], xreg[0][i]));
                __stcs((float4*)(outm + base),     make_float4(mreg[7][i], mreg[6][i], mreg[5][i], mreg[4][i]));
                __stcs((float4*)(outm + base + 4), make_float4(mreg[3][i], mreg[2][i], mreg[1][i], mreg[0][i]));
                __stcs((float4*)(outs + base),     make_float4(sreg[7][i], sreg[6][i], sreg[5][i], sreg[4][i]));
                __stcs((float4*)(outs + base + 4), make_float4(sreg[3][i], sreg[2][i], sreg[1][i], sreg[0][i]));
            }
        }
    }
}

extern "C" void kernel_launch(void* const* d_in, const int* in_sizes, int n_in,
                              void* d_out, int out_size) {
    const float* W    = (const float*)d_in[0];   // (T, NODE, NODE)
    const float* b    = (const float*)d_in[1];   // (T, NODE)
    const float* ne   = (const float*)d_in[2];   // (1, NODE, T)
    const float* eps0 = (const float*)d_in[3];   // (M, NODE)
    const float* eps  = (const float*)d_in[4];   // (T-1, M, NODE)
    float* out = (float*)d_out;                  // [x | m | s], each (M, NODE, T)

    k_prep<<<TT + 1, 256>>>(W, ne);
    k_chain<<<MM / RB, NTHREADS>>>(b, eps0, eps, out);
}